// round 13
// baseline (speedup 1.0000x reference)
#include <cuda_runtime.h>
#include <cuda_bf16.h>
#include <math.h>
#include <stdint.h>

// ---------------- scratch (no allocations allowed) ----------------
__device__ float g_Q[2048 * 4096];   // [S, NH*D]
__device__ float g_K[2048 * 1024];   // [S, NKV*D]
__device__ float g_V[2048 * 1024];   // [S, NKV*D]

// pre-split bf16 hi/lo operands
__device__ __nv_bfloat16 g_hsh[2048 * 4096], g_hsl[2048 * 4096];
__device__ __nv_bfloat16 g_Wqh[4096 * 4096], g_Wql[4096 * 4096];
__device__ __nv_bfloat16 g_Wkh[4096 * 1024], g_Wkl[4096 * 1024];
__device__ __nv_bfloat16 g_Wvh[4096 * 1024], g_Wvl[4096 * 1024];
__device__ __nv_bfloat16 g_Woh[4096 * 4096], g_Wol[4096 * 4096];
__device__ __nv_bfloat16 g_Ahh[2048 * 4096], g_Ahl[2048 * 4096];  // attn out hi/lo

// ---------------- PTX helpers ----------------
__device__ __forceinline__ uint32_t smem_addr(const void* p) {
    return (uint32_t)__cvta_generic_to_shared(p);
}
__device__ __forceinline__ void ldsm_x4(uint32_t* r, uint32_t addr) {
    asm volatile("ldmatrix.sync.aligned.m8n8.x4.shared.b16 {%0,%1,%2,%3}, [%4];\n"
                 : "=r"(r[0]), "=r"(r[1]), "=r"(r[2]), "=r"(r[3]) : "r"(addr));
}
__device__ __forceinline__ void ldsm_x2_t(uint32_t* r, uint32_t addr) {
    asm volatile("ldmatrix.sync.aligned.m8n8.x2.trans.shared.b16 {%0,%1}, [%2];\n"
                 : "=r"(r[0]), "=r"(r[1]) : "r"(addr));
}
__device__ __forceinline__ void mma_bf16(float* d, const uint32_t* a, const uint32_t* b) {
    asm volatile("mma.sync.aligned.m16n8k16.row.col.f32.bf16.bf16.f32 "
                 "{%0,%1,%2,%3}, {%4,%5,%6,%7}, {%8,%9}, {%0,%1,%2,%3};\n"
                 : "+f"(d[0]), "+f"(d[1]), "+f"(d[2]), "+f"(d[3])
                 : "r"(a[0]), "r"(a[1]), "r"(a[2]), "r"(a[3]), "r"(b[0]), "r"(b[1]));
}
__device__ __forceinline__ void cp_async16(uint32_t dst, const void* src) {
    asm volatile("cp.async.cg.shared.global [%0], [%1], 16;\n" :: "r"(dst), "l"(src));
}
__device__ __forceinline__ void cp_commit() {
    asm volatile("cp.async.commit_group;\n");
}
__device__ __forceinline__ void cp_wait0() {
    asm volatile("cp.async.wait_group 0;\n");
}

// ---------------- fp32 -> (hi, lo) bf16 split, vectorized ----------------
__global__ void split_fp32(const float* __restrict__ X,
                           __nv_bfloat16* __restrict__ H,
                           __nv_bfloat16* __restrict__ L, int n4) {
    int i = blockIdx.x * 256 + threadIdx.x;
    if (i >= n4) return;
    float4 v = ((const float4*)X)[i];
    float vv[4] = {v.x, v.y, v.z, v.w};
    __nv_bfloat16 h[4], l[4];
#pragma unroll
    for (int j = 0; j < 4; j++) {
        h[j] = __float2bfloat16(vv[j]);
        l[j] = __float2bfloat16(vv[j] - __bfloat162float(h[j]));
    }
    ((uint2*)H)[i] = *(uint2*)h;
    ((uint2*)L)[i] = *(uint2*)l;
}

// ---------------- pipelined tensor-core GEMM (pre-split bf16, 3-term) ----------------
// C[M,N] = A[M,K] @ B[K,N]; A/B given as bf16 hi+lo. Tiles 128x128x16,
// cp.async double-buffered (2 stages, 41KB static smem), 8 warps (2x4),
// each warp 64x32 via 4x4 m16n8k16; acc += Ah*Bh + Ah*Bl + Al*Bh.
__global__ __launch_bounds__(256) void mma_gemm_bf(const __nv_bfloat16* __restrict__ Ah,
                                                   const __nv_bfloat16* __restrict__ Al,
                                                   const __nv_bfloat16* __restrict__ Bh,
                                                   const __nv_bfloat16* __restrict__ Bl,
                                                   float* __restrict__ C,
                                                   int M, int N, int K) {
    __shared__ __align__(16) __nv_bfloat16 sA[2][2][128][24];   // [stage][h/l][row][k] 24KB
    __shared__ __align__(16) __nv_bfloat16 sB[2][2][16][136];   // [stage][h/l][k][n]   17KB

    const int t    = threadIdx.x;
    const int lane = t & 31;
    const int wid  = t >> 5;
    const int warp_m = wid & 1;
    const int warp_n = wid >> 1;
    const int bm = blockIdx.y * 128;
    const int bn = blockIdx.x * 128;

    // per-thread load slots (4 cp.async of 16B per stage)
    const int arow = t >> 1;            // 0..127
    const int akc  = (t & 1) * 8;       // 0 or 8
    const int brow = t >> 4;            // 0..15
    const int bnc  = (t & 15) * 8;      // 0..120

    auto load_tile = [&](int it, int st) {
        int k0 = it * 16;
        size_t sa = (size_t)(bm + arow) * K + k0 + akc;
        cp_async16(smem_addr(&sA[st][0][arow][akc]), Ah + sa);
        cp_async16(smem_addr(&sA[st][1][arow][akc]), Al + sa);
        size_t sb = (size_t)(k0 + brow) * N + bn + bnc;
        cp_async16(smem_addr(&sB[st][0][brow][bnc]), Bh + sb);
        cp_async16(smem_addr(&sB[st][1][brow][bnc]), Bl + sb);
    };

    float acc[4][4][4];
#pragma unroll
    for (int mi = 0; mi < 4; mi++)
#pragma unroll
        for (int ni = 0; ni < 4; ni++)
#pragma unroll
            for (int r = 0; r < 4; r++) acc[mi][ni][r] = 0.f;

    const int NT = K / 16;
    load_tile(0, 0);
    cp_commit();

    for (int it = 0; it < NT; it++) {
        cp_wait0();
        __syncthreads();                 // stage (it&1) ready; all compute on it-1 done
        const int b = it & 1;
        if (it + 1 < NT) { load_tile(it + 1, b ^ 1); cp_commit(); }

        uint32_t ah[4][4], al[4][4];
#pragma unroll
        for (int mi = 0; mi < 4; mi++) {
            int row = warp_m * 64 + mi * 16 + (lane & 15);
            int col = (lane >> 4) << 3;
            ldsm_x4(ah[mi], smem_addr(&sA[b][0][row][col]));
            ldsm_x4(al[mi], smem_addr(&sA[b][1][row][col]));
        }
        uint32_t bh[4][2], bl[4][2];
#pragma unroll
        for (int ni = 0; ni < 4; ni++) {
            int row = lane & 15;
            int col = warp_n * 32 + ni * 8;
            ldsm_x2_t(bh[ni], smem_addr(&sB[b][0][row][col]));
            ldsm_x2_t(bl[ni], smem_addr(&sB[b][1][row][col]));
        }
#pragma unroll
        for (int mi = 0; mi < 4; mi++)
#pragma unroll
            for (int ni = 0; ni < 4; ni++) {
                mma_bf16(acc[mi][ni], ah[mi], bh[ni]);
                mma_bf16(acc[mi][ni], ah[mi], bl[ni]);
                mma_bf16(acc[mi][ni], al[mi], bh[ni]);
            }
        __syncthreads();                 // compute(b) done before b is reloaded at it+2
    }

    const int gid = lane >> 2;
    const int tid = lane & 3;
#pragma unroll
    for (int mi = 0; mi < 4; mi++)
#pragma unroll
        for (int ni = 0; ni < 4; ni++) {
            int row = bm + warp_m * 64 + mi * 16 + gid;
            int col = bn + warp_n * 32 + ni * 8 + tid * 2;
            C[(size_t)row * N + col]           = acc[mi][ni][0];
            C[(size_t)row * N + col + 1]       = acc[mi][ni][1];
            C[(size_t)(row + 8) * N + col]     = acc[mi][ni][2];
            C[(size_t)(row + 8) * N + col + 1] = acc[mi][ni][3];
        }
}

// ---------------- RoPE (in-place) — UNCHANGED (proven) ----------------
__global__ void rope_naive(float* __restrict__ X, const int* __restrict__ pos_ids, int nh) {
    int idx = blockIdx.x * 256 + threadIdx.x;
    int total = 2048 * nh * 64;
    if (idx >= total) return;
    int i = idx % 64;
    int h = (idx / 64) % nh;
    int s = idx / (64 * nh);
    const float LN10000 = 9.210340371976184f;
    float inv = __expf(-((float)(2 * i) / 128.0f) * LN10000);
    float ang = (float)pos_ids[s] * inv;
    float c = cosf(ang);
    float sn = sinf(ang);
    float* row = X + (size_t)s * (nh * 128) + h * 128;
    float x1 = row[i];
    float x2 = row[i + 64];
    row[i]      = x1 * c - x2 * sn;
    row[i + 64] = x2 * c + x1 * sn;
}

// ---------------- attention: 4 q-rows/block; epilogue writes bf16 hi/lo ----------------
__global__ __launch_bounds__(256) void attn_q4(const float* __restrict__ Q,
                                               const float* __restrict__ K,
                                               const float* __restrict__ V,
                                               __nv_bfloat16* __restrict__ Oh,
                                               __nv_bfloat16* __restrict__ Ol) {
    __shared__ float sc[4][2048];
    __shared__ float qs[4][128];
    __shared__ float red[256];

    const int qb = blockIdx.x;
    const int h  = blockIdx.y;
    const int kh = h >> 2;
    const int t  = threadIdx.x;
    const int q0 = qb * 4;
    const int qmax = q0 + 3;

    const float scale = 0.08838834764831845f;

    for (int i = t; i < 512; i += 256) {
        int r = i >> 7;
        int d = i & 127;
        qs[r][d] = Q[(size_t)(q0 + r) * 4096 + h * 128 + d];
    }
    __syncthreads();

    const int r  = t & 3;
    const int ks = t >> 2;
    float mx = -INFINITY;
    for (int k = ks; k <= qmax; k += 64) {
        const float* krow = K + (size_t)k * 1024 + kh * 128;
        float s = 0.f;
#pragma unroll 8
        for (int d4 = 0; d4 < 128; d4 += 4) {
            float4 kv = *(const float4*)(krow + d4);
            float4 qv = *(const float4*)&qs[r][d4];
            s += qv.x * kv.x + qv.y * kv.y + qv.z * kv.z + qv.w * kv.w;
        }
        s *= scale;
        if (k > q0 + r) s = -1e30f;
        sc[r][k] = s;
        mx = fmaxf(mx, s);
    }

    red[t] = mx;
    __syncthreads();
    for (int off = 128; off >= 4; off >>= 1) {
        if (t < off) red[t] = fmaxf(red[t], red[t + off]);
        __syncthreads();
    }
    float mrow = red[r];
    __syncthreads();

    float sum = 0.f;
    for (int k = ks; k <= qmax; k += 64) {
        float p = __expf(sc[r][k] - mrow);
        sc[r][k] = p;
        sum += p;
    }
    red[t] = sum;
    __syncthreads();
    for (int off = 128; off >= 4; off >>= 1) {
        if (t < off) red[t] += red[t + off];
        __syncthreads();
    }

    const int d   = t & 127;
    const int rp0 = (t >> 7) * 2;
    const int rp1 = rp0 + 1;
    const float* vcol = V + (size_t)kh * 128 + d;

    float acc0 = 0.f, acc1 = 0.f;
    for (int k = 0; k <= qmax; k++) {
        float v = vcol[(size_t)k * 1024];
        acc0 += sc[rp0][k] * v;
        acc1 += sc[rp1][k] * v;
    }

    float o0 = acc0 / red[rp0];
    float o1 = acc1 / red[rp1];
    size_t i0 = (size_t)(q0 + rp0) * 4096 + h * 128 + d;
    size_t i1 = (size_t)(q0 + rp1) * 4096 + h * 128 + d;
    __nv_bfloat16 h0 = __float2bfloat16(o0);
    __nv_bfloat16 h1 = __float2bfloat16(o1);
    Oh[i0] = h0;  Ol[i0] = __float2bfloat16(o0 - __bfloat162float(h0));
    Oh[i1] = h1;  Ol[i1] = __float2bfloat16(o1 - __bfloat162float(h1));
}

// ---------------- launch ----------------
extern "C" void kernel_launch(void* const* d_in, const int* in_sizes, int n_in,
                              void* d_out, int out_size) {
    // Size-driven input identification (identical to passing rounds).
    int i16[2] = {-1, -1}, n16 = 0;
    int i4[2]  = {-1, -1}, n4  = 0;
    int iHS = -1, iPOS = -1;
    for (int i = 0; i < 6; i++) {
        int s = in_sizes[i];
        if (s == 16777216)      { if (n16 < 2) i16[n16++] = i; }
        else if (s == 4194304)  { if (n4  < 2) i4[n4++]   = i; }
        else if (s == 8388608)  iHS = i;
        else                    iPOS = i;   // 2048
    }
    int iWq, iWo;
    if (i16[1] == i16[0] + 1) { iWo = i16[0]; iWq = i16[1]; }
    else                      { iWq = i16[0]; iWo = i16[1]; }
    const int iWk = i4[0];
    const int iWv = i4[1];

    const float* hs  = (const float*)d_in[iHS];
    const int*   pos = (const int*)d_in[iPOS];
    const float* Wq  = (const float*)d_in[iWq];
    const float* Wk  = (const float*)d_in[iWk];
    const float* Wv  = (const float*)d_in[iWv];
    const float* Wo  = (const float*)d_in[iWo];
    float* out = (float*)d_out;

    float *Q, *K, *V;
    cudaGetSymbolAddress((void**)&Q, g_Q);
    cudaGetSymbolAddress((void**)&K, g_K);
    cudaGetSymbolAddress((void**)&V, g_V);

    __nv_bfloat16 *hsh, *hsl, *Wqh, *Wql, *Wkh, *Wkl, *Wvh, *Wvl, *Woh, *Wol, *Ahh, *Ahl;
    cudaGetSymbolAddress((void**)&hsh, g_hsh);
    cudaGetSymbolAddress((void**)&hsl, g_hsl);
    cudaGetSymbolAddress((void**)&Wqh, g_Wqh);
    cudaGetSymbolAddress((void**)&Wql, g_Wql);
    cudaGetSymbolAddress((void**)&Wkh, g_Wkh);
    cudaGetSymbolAddress((void**)&Wkl, g_Wkl);
    cudaGetSymbolAddress((void**)&Wvh, g_Wvh);
    cudaGetSymbolAddress((void**)&Wvl, g_Wvl);
    cudaGetSymbolAddress((void**)&Woh, g_Woh);
    cudaGetSymbolAddress((void**)&Wol, g_Wol);
    cudaGetSymbolAddress((void**)&Ahh, g_Ahh);
    cudaGetSymbolAddress((void**)&Ahl, g_Ahl);

    // ---- pre-split all GEMM operands into bf16 hi/lo ----
    {
        int n;
        n = 2048 * 4096 / 4; split_fp32<<<(n + 255) / 256, 256>>>(hs, hsh, hsl, n);
        n = 4096 * 4096 / 4; split_fp32<<<(n + 255) / 256, 256>>>(Wq, Wqh, Wql, n);
        n = 4096 * 1024 / 4; split_fp32<<<(n + 255) / 256, 256>>>(Wk, Wkh, Wkl, n);
        n = 4096 * 1024 / 4; split_fp32<<<(n + 255) / 256, 256>>>(Wv, Wvh, Wvl, n);
        n = 4096 * 4096 / 4; split_fp32<<<(n + 255) / 256, 256>>>(Wo, Woh, Wol, n);
    }

    // QKV projections (pipelined tensor-core GEMM)
    {
        dim3 gq(4096 / 128, 2048 / 128);
        mma_gemm_bf<<<gq, 256>>>(hsh, hsl, Wqh, Wql, Q, 2048, 4096, 4096);
        dim3 gkv(1024 / 128, 2048 / 128);
        mma_gemm_bf<<<gkv, 256>>>(hsh, hsl, Wkh, Wkl, K, 2048, 1024, 4096);
        mma_gemm_bf<<<gkv, 256>>>(hsh, hsl, Wvh, Wvl, V, 2048, 1024, 4096);
    }

    // RoPE on Q (32 heads) and K (8 heads)
    {
        int totq = 2048 * 32 * 64;
        rope_naive<<<(totq + 255) / 256, 256>>>(Q, pos, 32);
        int totk = 2048 * 8 * 64;
        rope_naive<<<(totk + 255) / 256, 256>>>(K, pos, 8);
    }

    // Attention (4 q-rows per block; writes bf16 hi/lo directly)
    {
        dim3 ga(512, 32);
        attn_q4<<<ga, 256>>>(Q, K, V, Ahh, Ahl);
    }

    // Output projection (pipelined tensor-core GEMM)
    {
        dim3 go(4096 / 128, 2048 / 128);
        mma_gemm_bf<<<go, 256>>>(Ahh, Ahl, Woh, Wol, out, 2048, 4096, 4096);
    }
}